// round 15
// baseline (speedup 1.0000x reference)
#include <cuda_runtime.h>
#include <math.h>

// Skipgram negative-sampling loss — persistent single-wave kernel with a
// double-buffered cp.async pipeline across batch elements: while element i
// is consumed from smem, element i+1's 10 negative rows (and its center/pos
// LDGs) are already in flight. Warp never drains its memory pipeline.
// 683 blocks x 128 threads (4 warps), 6 elements per warp, 40KB smem
// -> 5 blocks/SM, one wave.
// Inputs (metadata order):
//   d_in[0] center_id       int32 [B]
//   d_in[1] pos_context_id  int32 [B]
//   d_in[2] neg_context_ids int32 [B, K]
//   d_in[3] W_in            f32   [VOCAB, DIM]
//   d_in[4] W_out           f32   [VOCAB, DIM]
// Output: scalar f32 = -(sum log_sigmoid(pos_score) + sum log_sigmoid(-neg_score))

#define BATCH 16384
#define KNEG  10
#define DIMV4 32          // 128 floats = 32 float4 per row
#define WPB   4           // warps per block (128 threads)
#define EPW   6           // batch elements per warp (pipelined)
#define NBLKP 683         // ceil(16384 / (4*6)); 683*24 = 16392 (8 masked)
#define NPAD  768         // padded partial count (6*128)

__device__ float g_partial[NPAD];        // slots >= NBLKP stay 0 forever
__device__ unsigned int g_count = 0;     // reset by last block each call

__device__ __forceinline__ float log_sigmoid(float x) {
    return fminf(x, 0.0f) - log1pf(__expf(-fabsf(x)));
}

__device__ __forceinline__ void cp_async16(void* smem_dst, const void* gmem_src) {
    unsigned int s = (unsigned int)__cvta_generic_to_shared(smem_dst);
    asm volatile("cp.async.cg.shared.global [%0], [%1], 16;\n" :: "r"(s), "l"(gmem_src));
}

__global__ __launch_bounds__(128) void skipgram_fused(
    const int* __restrict__ center_id,
    const int* __restrict__ pos_id,
    const int* __restrict__ neg_ids,
    const float4* __restrict__ Win,
    const float4* __restrict__ Wout,
    float* __restrict__ out)
{
    // Double-buffered staging: 2 x 10 neg rows per warp. 4*2*10*32*16B = 40KB.
    __shared__ float4 buf[WPB][2][KNEG][32];
    __shared__ float s[WPB];
    __shared__ bool is_last;

    const int lane = threadIdx.x & 31;
    const int w    = threadIdx.x >> 5;
    const int g    = blockIdx.x * WPB + w;   // global warp id
    const int base = g * EPW;

    float loss = 0.f;

    // ---- Prologue: launch element 0's loads ----
    int   cur_valid = (base < BATCH);
    float4 c_cur = make_float4(0.f, 0.f, 0.f, 0.f);
    float4 p_cur = make_float4(0.f, 0.f, 0.f, 0.f);
    if (cur_valid) {
        int my = 0;
        if (lane < KNEG) my = neg_ids[base * KNEG + lane];
#pragma unroll
        for (int k = 0; k < KNEG; ++k) {
            const unsigned id = (unsigned)__shfl_sync(0xffffffffu, my, k);
            cp_async16(&buf[w][0][k][lane], Wout + (id * DIMV4 + (unsigned)lane));
        }
        const unsigned cid = (unsigned)center_id[base];
        const unsigned pid = (unsigned)pos_id[base];
        c_cur = Win [cid * DIMV4 + (unsigned)lane];
        p_cur = Wout[pid * DIMV4 + (unsigned)lane];
    }
    asm volatile("cp.async.commit_group;\n" ::: "memory");

#pragma unroll
    for (int i = 0; i < EPW; ++i) {
        const int bb = i & 1;        // current buffer
        const int nb_ = bb ^ 1;      // next buffer

        // ---- Issue element i+1's loads BEFORE consuming element i ----
        int next_valid = 0;
        float4 c_nxt = make_float4(0.f, 0.f, 0.f, 0.f);
        float4 p_nxt = make_float4(0.f, 0.f, 0.f, 0.f);
        if (i + 1 < EPW) {
            const int bn = base + i + 1;
            next_valid = (bn < BATCH);
            if (next_valid) {
                int my = 0;
                if (lane < KNEG) my = neg_ids[bn * KNEG + lane];
#pragma unroll
                for (int k = 0; k < KNEG; ++k) {
                    const unsigned id = (unsigned)__shfl_sync(0xffffffffu, my, k);
                    cp_async16(&buf[w][nb_][k][lane],
                               Wout + (id * DIMV4 + (unsigned)lane));
                }
                const unsigned cid = (unsigned)center_id[bn];
                const unsigned pid = (unsigned)pos_id[bn];
                c_nxt = Win [cid * DIMV4 + (unsigned)lane];
                p_nxt = Wout[pid * DIMV4 + (unsigned)lane];
            }
            asm volatile("cp.async.commit_group;\n" ::: "memory");
            asm volatile("cp.async.wait_group 1;\n" ::: "memory");  // element i done
        } else {
            asm volatile("cp.async.wait_group 0;\n" ::: "memory");  // drain
        }
        __syncwarp();

        // ---- Consume element i ----
        if (cur_valid) {
            float4 na = make_float4(0.f, 0.f, 0.f, 0.f);
            float4 nb2 = make_float4(0.f, 0.f, 0.f, 0.f);
#pragma unroll
            for (int k = 0; k < KNEG; k += 2) {
                const float4 va = buf[w][bb][k][lane];
                const float4 vb = buf[w][bb][k + 1][lane];
                na.x  += va.x; na.y  += va.y; na.z  += va.z; na.w  += va.w;
                nb2.x += vb.x; nb2.y += vb.y; nb2.z += vb.z; nb2.w += vb.w;
            }
            const float4 ns = make_float4(na.x + nb2.x, na.y + nb2.y,
                                          na.z + nb2.z, na.w + nb2.w);

            float pd = c_cur.x * p_cur.x + c_cur.y * p_cur.y
                     + c_cur.z * p_cur.z + c_cur.w * p_cur.w;
            float nd = c_cur.x * ns.x + c_cur.y * ns.y
                     + c_cur.z * ns.z + c_cur.w * ns.w;

#pragma unroll
            for (int o = 16; o > 0; o >>= 1) {
                pd += __shfl_xor_sync(0xffffffffu, pd, o);
                nd += __shfl_xor_sync(0xffffffffu, nd, o);
            }

            loss += log_sigmoid(pd) + log_sigmoid(-nd);
        }

        cur_valid = next_valid;
        c_cur = c_nxt;
        p_cur = p_nxt;
    }

    if (lane == 0)
        s[w] = loss;
    __syncthreads();

    // ---- Per-block epilogue: warp 0 sums the 4 warp results ----
    if (w == 0) {
        float t = (lane < WPB) ? s[lane] : 0.f;
#pragma unroll
        for (int o = 2; o > 0; o >>= 1)
            t += __shfl_xor_sync(0xffffffffu, t, o);

        if (lane == 0) {
            g_partial[blockIdx.x] = t;
            __threadfence();
            unsigned int old = atomicAdd(&g_count, 1u);
            is_last = (old == NBLKP - 1);
        }
    }
    __syncthreads();

    if (is_last) {
        // Deterministic fixed-order reduction: 768 slots over 128 threads
        // (slots >= 683 are never written and remain 0).
        float t = 0.f;
#pragma unroll
        for (int j = 0; j < NPAD / 128; ++j)
            t += g_partial[threadIdx.x + j * 128];

#pragma unroll
        for (int o = 16; o > 0; o >>= 1)
            t += __shfl_xor_sync(0xffffffffu, t, o);

        __shared__ float s2[WPB];
        if (lane == 0) s2[w] = t;
        __syncthreads();

        if (w == 0) {
            float tot = (lane < WPB) ? s2[lane] : 0.f;
#pragma unroll
            for (int o = 2; o > 0; o >>= 1)
                tot += __shfl_xor_sync(0xffffffffu, tot, o);
            if (lane == 0) {
                out[0] = -tot;
                g_count = 0;   // reset for next graph replay
            }
        }
    }
}

extern "C" void kernel_launch(void* const* d_in, const int* in_sizes, int n_in,
                              void* d_out, int out_size)
{
    const int*    center_id = (const int*)   d_in[0];
    const int*    pos_id    = (const int*)   d_in[1];
    const int*    neg_ids   = (const int*)   d_in[2];
    const float4* Win       = (const float4*)d_in[3];
    const float4* Wout      = (const float4*)d_in[4];
    float* out = (float*)d_out;

    skipgram_fused<<<NBLKP, 128>>>(center_id, pos_id, neg_ids, Win, Wout, out);
}

// round 16
// speedup vs baseline: 1.0191x; 1.0191x over previous
#include <cuda_runtime.h>
#include <math.h>

// Skipgram negative-sampling loss — persistent single-wave fused kernel.
// FINAL: best-measured configuration (14.85us ≈ 98% of the GB300 LTS
// sector-service cap for the irreducible 100.7MB random-row gather).
//   - 683 blocks x 256 threads, 40KB smem -> 5 blocks/SM, exactly one wave
//   - one warp handles 3 batch elements sequentially
//   - per element: 10 negative rows gathered via cp.async.cg (single burst,
//     one commit group, lane-sliced 512B rows), center/pos via LDG.128
//   - sum-over-negatives folded to one dot product (dot(sum_k neg_k, center))
//   - deterministic tail: single-counter last-block completion, fixed-order
//     reductions everywhere
// Inputs (metadata order):
//   d_in[0] center_id       int32 [B]
//   d_in[1] pos_context_id  int32 [B]
//   d_in[2] neg_context_ids int32 [B, K]
//   d_in[3] W_in            f32   [VOCAB, DIM]
//   d_in[4] W_out           f32   [VOCAB, DIM]
// Output: scalar f32 = -(sum log_sigmoid(pos_score) + sum log_sigmoid(-neg_score))

#define BATCH 16384
#define KNEG  10
#define DIMV4 32          // 128 floats = 32 float4 per row
#define WPB   8           // warps per block
#define EPW   3           // batch elements per warp (sequential)
#define NBLKP 683         // ceil(16384 / (8*3)); 683*24 = 16392 (8 masked)
#define NPAD  768         // padded partial count (3*256)

__device__ float g_partial[NPAD];        // slots >= NBLKP stay 0 forever
__device__ unsigned int g_count = 0;     // reset by last block each call

__device__ __forceinline__ float log_sigmoid(float x) {
    return fminf(x, 0.0f) - log1pf(__expf(-fabsf(x)));
}

__device__ __forceinline__ void cp_async16(void* smem_dst, const void* gmem_src) {
    unsigned int s = (unsigned int)__cvta_generic_to_shared(smem_dst);
    asm volatile("cp.async.cg.shared.global [%0], [%1], 16;\n" :: "r"(s), "l"(gmem_src));
}

__global__ __launch_bounds__(256) void skipgram_fused(
    const int* __restrict__ center_id,
    const int* __restrict__ pos_id,
    const int* __restrict__ neg_ids,
    const float4* __restrict__ Win,
    const float4* __restrict__ Wout,
    float* __restrict__ out)
{
    // Staging: 10 neg rows per warp, lane-sliced. 8*10*32*16B = 40KB.
    __shared__ float4 buf[WPB][KNEG][32];
    __shared__ float s[WPB];
    __shared__ bool is_last;

    const int lane = threadIdx.x & 31;
    const int w    = threadIdx.x >> 5;
    const int g    = blockIdx.x * WPB + w;   // global warp id

    float loss = 0.f;   // identical value on all lanes

#pragma unroll
    for (int i = 0; i < EPW; ++i) {
        const int b = g * EPW + i;
        if (b < BATCH) {
            // ---- Indices ----
            const int cid = center_id[b];
            const int pid = pos_id[b];
            int my_nid = 0;
            if (lane < KNEG) my_nid = neg_ids[b * KNEG + lane];

            // ---- Async gather of all 10 negative rows (single burst) ----
            // In-order issue guarantees the previous iteration's smem reads
            // were consumed before these writes.
#pragma unroll
            for (int k = 0; k < KNEG; ++k) {
                const unsigned id = (unsigned)__shfl_sync(0xffffffffu, my_nid, k);
                cp_async16(&buf[w][k][lane], Wout + (id * DIMV4 + (unsigned)lane));
            }
            asm volatile("cp.async.commit_group;\n" ::: "memory");

            // ---- Direct loads overlap with the async gather ----
            const float4 c = Win [(unsigned)cid * DIMV4 + (unsigned)lane];
            const float4 p = Wout[(unsigned)pid * DIMV4 + (unsigned)lane];

            asm volatile("cp.async.wait_group 0;\n" ::: "memory");
            __syncwarp();

            // ---- Reduce: two accumulator chains over smem rows ----
            float4 na = make_float4(0.f, 0.f, 0.f, 0.f);
            float4 nb = make_float4(0.f, 0.f, 0.f, 0.f);
#pragma unroll
            for (int k = 0; k < KNEG; k += 2) {
                const float4 va = buf[w][k][lane];
                const float4 vb = buf[w][k + 1][lane];
                na.x += va.x; na.y += va.y; na.z += va.z; na.w += va.w;
                nb.x += vb.x; nb.y += vb.y; nb.z += vb.z; nb.w += vb.w;
            }
            const float4 ns = make_float4(na.x + nb.x, na.y + nb.y,
                                          na.z + nb.z, na.w + nb.w);

            float pd = c.x * p.x + c.y * p.y + c.z * p.z + c.w * p.w;
            float nd = c.x * ns.x + c.y * ns.y + c.z * ns.z + c.w * ns.w;

#pragma unroll
            for (int o = 16; o > 0; o >>= 1) {
                pd += __shfl_xor_sync(0xffffffffu, pd, o);
                nd += __shfl_xor_sync(0xffffffffu, nd, o);
            }

            loss += log_sigmoid(pd) + log_sigmoid(-nd);
        }
    }

    if (lane == 0)
        s[w] = loss;
    __syncthreads();

    // ---- Per-block epilogue: warp 0 sums the 8 warp results ----
    if (w == 0) {
        float t = (lane < WPB) ? s[lane] : 0.f;
#pragma unroll
        for (int o = 4; o > 0; o >>= 1)
            t += __shfl_xor_sync(0xffffffffu, t, o);

        if (lane == 0) {
            g_partial[blockIdx.x] = t;
            __threadfence();
            unsigned int old = atomicAdd(&g_count, 1u);
            is_last = (old == NBLKP - 1);
        }
    }
    __syncthreads();

    if (is_last) {
        // Deterministic fixed-order reduction: 768 slots over 256 threads
        // (slots >= 683 are never written and remain 0).
        float t = g_partial[threadIdx.x]
                + g_partial[threadIdx.x + 256]
                + g_partial[threadIdx.x + 512];

#pragma unroll
        for (int o = 16; o > 0; o >>= 1)
            t += __shfl_xor_sync(0xffffffffu, t, o);

        __shared__ float s2[WPB];
        if (lane == 0) s2[w] = t;
        __syncthreads();

        if (w == 0) {
            float tot = (lane < WPB) ? s2[lane] : 0.f;
#pragma unroll
            for (int o = 4; o > 0; o >>= 1)
                tot += __shfl_xor_sync(0xffffffffu, tot, o);
            if (lane == 0) {
                out[0] = -tot;
                g_count = 0;   // reset for next graph replay
            }
        }
    }
}

extern "C" void kernel_launch(void* const* d_in, const int* in_sizes, int n_in,
                              void* d_out, int out_size)
{
    const int*    center_id = (const int*)   d_in[0];
    const int*    pos_id    = (const int*)   d_in[1];
    const int*    neg_ids   = (const int*)   d_in[2];
    const float4* Win       = (const float4*)d_in[3];
    const float4* Wout      = (const float4*)d_in[4];
    float* out = (float*)d_out;

    skipgram_fused<<<NBLKP, 256>>>(center_id, pos_id, neg_ids, Win, Wout, out);
}

// round 17
// speedup vs baseline: 1.2030x; 1.1805x over previous
#include <cuda_runtime.h>
#include <math.h>

// Skipgram negative-sampling loss — persistent single-wave fused kernel.
// Best-measured shape (14.85us ≈ LTS roofline) + hoisted index loads:
// all 3 elements' indices are fetched up-front so each element's 10-row
// cp.async burst issues with zero dependent-load prefix.
//   - 683 blocks x 256 threads, 40KB smem -> 5 blocks/SM, exactly one wave
//   - one warp handles 3 batch elements sequentially
//   - per element: 10 negative rows via cp.async.cg (single burst),
//     center/pos via LDG.128; dot(sum_k neg_k, center) folding
//   - deterministic tail: single-counter last-block completion
// Inputs (metadata order):
//   d_in[0] center_id       int32 [B]
//   d_in[1] pos_context_id  int32 [B]
//   d_in[2] neg_context_ids int32 [B, K]
//   d_in[3] W_in            f32   [VOCAB, DIM]
//   d_in[4] W_out           f32   [VOCAB, DIM]
// Output: scalar f32 = -(sum log_sigmoid(pos_score) + sum log_sigmoid(-neg_score))

#define BATCH 16384
#define KNEG  10
#define DIMV4 32          // 128 floats = 32 float4 per row
#define WPB   8           // warps per block
#define EPW   3           // batch elements per warp (sequential)
#define NBLKP 683         // ceil(16384 / (8*3)); 683*24 = 16392 (8 masked)
#define NPAD  768         // padded partial count (3*256)

__device__ float g_partial[NPAD];        // slots >= NBLKP stay 0 forever
__device__ unsigned int g_count = 0;     // reset by last block each call

__device__ __forceinline__ float log_sigmoid(float x) {
    return fminf(x, 0.0f) - log1pf(__expf(-fabsf(x)));
}

__device__ __forceinline__ void cp_async16(void* smem_dst, const void* gmem_src) {
    unsigned int s = (unsigned int)__cvta_generic_to_shared(smem_dst);
    asm volatile("cp.async.cg.shared.global [%0], [%1], 16;\n" :: "r"(s), "l"(gmem_src));
}

__global__ __launch_bounds__(256, 5) void skipgram_fused(
    const int* __restrict__ center_id,
    const int* __restrict__ pos_id,
    const int* __restrict__ neg_ids,
    const float4* __restrict__ Win,
    const float4* __restrict__ Wout,
    float* __restrict__ out)
{
    // Staging: 10 neg rows per warp, lane-sliced. 8*10*32*16B = 40KB.
    __shared__ float4 buf[WPB][KNEG][32];
    __shared__ float s[WPB];
    __shared__ bool is_last;

    const int lane = threadIdx.x & 31;
    const int w    = threadIdx.x >> 5;
    const int g    = blockIdx.x * WPB + w;   // global warp id

    // ---- Hoisted index loads: all EPW elements' indices, independent ----
    unsigned cid[EPW], pid[EPW];
    int my_nid[EPW];
    int valid[EPW];
#pragma unroll
    for (int i = 0; i < EPW; ++i) {
        const int b = g * EPW + i;
        valid[i] = (b < BATCH);
        const int bs = valid[i] ? b : 0;     // clamp: safe dummy reads
        cid[i] = (unsigned)center_id[bs];
        pid[i] = (unsigned)pos_id[bs];
        my_nid[i] = (lane < KNEG) ? neg_ids[bs * KNEG + lane] : 0;
    }

    float loss = 0.f;   // identical value on all lanes

#pragma unroll
    for (int i = 0; i < EPW; ++i) {
        if (valid[i]) {
            // ---- Async gather of all 10 negative rows (single burst) ----
            // Indices already resident; burst issues immediately.
#pragma unroll
            for (int k = 0; k < KNEG; ++k) {
                const unsigned id = (unsigned)__shfl_sync(0xffffffffu, my_nid[i], k);
                cp_async16(&buf[w][k][lane], Wout + (id * DIMV4 + (unsigned)lane));
            }
            asm volatile("cp.async.commit_group;\n" ::: "memory");

            // ---- Direct loads overlap with the async gather ----
            const float4 c = Win [cid[i] * DIMV4 + (unsigned)lane];
            const float4 p = Wout[pid[i] * DIMV4 + (unsigned)lane];

            asm volatile("cp.async.wait_group 0;\n" ::: "memory");
            __syncwarp();

            // ---- Reduce: two accumulator chains over smem rows ----
            float4 na = make_float4(0.f, 0.f, 0.f, 0.f);
            float4 nb = make_float4(0.f, 0.f, 0.f, 0.f);
#pragma unroll
            for (int k = 0; k < KNEG; k += 2) {
                const float4 va = buf[w][k][lane];
                const float4 vb = buf[w][k + 1][lane];
                na.x += va.x; na.y += va.y; na.z += va.z; na.w += va.w;
                nb.x += vb.x; nb.y += vb.y; nb.z += vb.z; nb.w += vb.w;
            }
            const float4 ns = make_float4(na.x + nb.x, na.y + nb.y,
                                          na.z + nb.z, na.w + nb.w);

            float pd = c.x * p.x + c.y * p.y + c.z * p.z + c.w * p.w;
            float nd = c.x * ns.x + c.y * ns.y + c.z * ns.z + c.w * ns.w;

#pragma unroll
            for (int o = 16; o > 0; o >>= 1) {
                pd += __shfl_xor_sync(0xffffffffu, pd, o);
                nd += __shfl_xor_sync(0xffffffffu, nd, o);
            }

            loss += log_sigmoid(pd) + log_sigmoid(-nd);
        }
    }

    if (lane == 0)
        s[w] = loss;
    __syncthreads();

    // ---- Per-block epilogue: warp 0 sums the 8 warp results ----
    if (w == 0) {
        float t = (lane < WPB) ? s[lane] : 0.f;
#pragma unroll
        for (int o = 4; o > 0; o >>= 1)
            t += __shfl_xor_sync(0xffffffffu, t, o);

        if (lane == 0) {
            g_partial[blockIdx.x] = t;
            __threadfence();
            unsigned int old = atomicAdd(&g_count, 1u);
            is_last = (old == NBLKP - 1);
        }
    }
    __syncthreads();

    if (is_last) {
        // Deterministic fixed-order reduction: 768 slots over 256 threads
        // (slots >= 683 are never written and remain 0).
        float t = g_partial[threadIdx.x]
                + g_partial[threadIdx.x + 256]
                + g_partial[threadIdx.x + 512];

#pragma unroll
        for (int o = 16; o > 0; o >>= 1)
            t += __shfl_xor_sync(0xffffffffu, t, o);

        __shared__ float s2[WPB];
        if (lane == 0) s2[w] = t;
        __syncthreads();

        if (w == 0) {
            float tot = (lane < WPB) ? s2[lane] : 0.f;
#pragma unroll
            for (int o = 4; o > 0; o >>= 1)
                tot += __shfl_xor_sync(0xffffffffu, tot, o);
            if (lane == 0) {
                out[0] = -tot;
                g_count = 0;   // reset for next graph replay
            }
        }
    }
}

extern "C" void kernel_launch(void* const* d_in, const int* in_sizes, int n_in,
                              void* d_out, int out_size)
{
    const int*    center_id = (const int*)   d_in[0];
    const int*    pos_id    = (const int*)   d_in[1];
    const int*    neg_ids   = (const int*)   d_in[2];
    const float4* Win       = (const float4*)d_in[3];
    const float4* Wout      = (const float4*)d_in[4];
    float* out = (float*)d_out;

    skipgram_fused<<<NBLKP, 256>>>(center_id, pos_id, neg_ids, Win, Wout, out);
}